// round 3
// baseline (speedup 1.0000x reference)
#include <cuda_runtime.h>

#define BATCH 32
#define IMH 1024
#define IMW 1024
#define NBOX 96
#define WARPS 8
#define NTHREADS 256
#define ROWS_PER_WARP 4
#define ROWS_PER_BLOCK (WARPS * ROWS_PER_WARP)   // 32
#define GRID (BATCH * IMH / ROWS_PER_BLOCK)      // 1024
#define EP_STRIDE 1032                           // 1025 rounded up, float4-aligned

// Per-(batch,box) rectangle sums. Zero-initialized at module load; the last
// block resets it after reading so every graph replay starts clean.
__device__ float    g_boxsum[BATCH * NBOX];
__device__ unsigned g_done;

__global__ __launch_bounds__(NTHREADS)
void fused_kernel(const float* __restrict__ img, const int* __restrict__ bb,
                  float* __restrict__ out) {
    __shared__ __align__(16) float ep_s[WARPS * EP_STRIDE];
    __shared__ int4 sbox[NBOX];

    const int t    = threadIdx.x;
    const int lane = t & 31;
    const int w    = t >> 5;
    const int blocksPerBatch = IMH / ROWS_PER_BLOCK;   // 32
    const int b       = blockIdx.x / blocksPerBatch;
    const int rowBase = (blockIdx.x % blocksPerBatch) * ROWS_PER_BLOCK + w * ROWS_PER_WARP;

    float* ep = ep_s + w * EP_STRIDE;

    // One cooperative bbox load per block (96 int4 = 1.5 KB).
    if (t < NBOX) sbox[t] = ((const int4*)bb)[b * NBOX + t];
    __syncthreads();

    // Each lane serves boxes lane, lane+32, lane+64.
    int   bx1[3], bx2[3], by1[3], by2[3];
    bool  bval[3];
    float bacc[3];
#pragma unroll
    for (int k = 0; k < 3; k++) {
        int4 box = sbox[lane + 32 * k];
        bx1[k] = min(max(box.x, 0), IMW);
        by1[k] = min(max(box.y, 0), IMW);
        bx2[k] = min(max(box.z, 0), IMW);
        by2[k] = min(max(box.w, 0), IMW);
        bval[k] = (bx2[k] > bx1[k]) && (by2[k] > by1[k]);
        bacc[k] = 0.0f;
    }

    const float4* imgrow = (const float4*)(img + (size_t)b * IMH * IMW);

    for (int r = 0; r < ROWS_PER_WARP; ++r) {
        const int row = rowBase + r;

        // 1) Coalesced load: lane holds elements 128*j + 4*lane .. +3 for j=0..7.
        float4 v[8];
#pragma unroll
        for (int j = 0; j < 8; j++)
            v[j] = imgrow[(size_t)row * (IMW / 4) + lane + 32 * j];

        // 2) Per-(lane, segment) 4-element sums.
        float s[8];
#pragma unroll
        for (int j = 0; j < 8; j++)
            s[j] = (v[j].x + v[j].y) + (v[j].z + v[j].w);

        // 3) Eight independent warp scans (one per 128-wide segment), chained
        //    only through the scalar segment base.
        float excl[8];
        float base = 0.0f;
#pragma unroll
        for (int j = 0; j < 8; j++) {
            float sc = s[j];
#pragma unroll
            for (int o = 1; o < 32; o <<= 1) {
                float u = __shfl_up_sync(0xffffffffu, sc, o);
                if (lane >= o) sc += u;
            }
            excl[j] = (sc - s[j]) + base;
            base += __shfl_sync(0xffffffffu, sc, 31);   // segment total
        }

        // 4) Single SMEM write per row: exclusive prefixes, STS.128, conflict-free.
#pragma unroll
        for (int j = 0; j < 8; j++) {
            float4 p;
            p.x = excl[j];
            p.y = p.x + v[j].x;
            p.z = p.y + v[j].y;
            p.w = p.z + v[j].z;
            *(float4*)(ep + 128 * j + 4 * lane) = p;
        }
        if (lane == 31) ep[IMW] = base;   // prefix(1024) = row total
        __syncwarp();

        // 5) Serve this row for all 96 boxes (3 per lane).
#pragma unroll
        for (int k = 0; k < 3; k++) {
            if (bval[k] && by1[k] <= row && row < by2[k])
                bacc[k] += ep[bx2[k]] - ep[bx1[k]];
        }
        __syncwarp();   // ep reused next row
    }

#pragma unroll
    for (int k = 0; k < 3; k++)
        if (bval[k] && bacc[k] != 0.0f)
            atomicAdd(&g_boxsum[b * NBOX + lane + 32 * k], bacc[k]);

    // ---- last-block epilogue: loss + state reset ----
    __shared__ unsigned lastflag;
    __threadfence();
    if (t == 0) {
        unsigned vdone = atomicAdd(&g_done, 1u);
        lastflag = (vdone == (unsigned)(gridDim.x - 1));
    }
    __syncthreads();

    if (lastflag) {
        float sum = 0.0f;
        for (int i = t; i < BATCH * NBOX; i += NTHREADS) {
            float sv = __ldcg(&g_boxsum[i]);
            g_boxsum[i] = 0.0f;                 // reset for next replay
            float d = 1.0f - sv;                // invalid boxes stayed 0 -> contribute 1
            sum += (d > 0.0f) ? d : 0.0f;
        }
        __shared__ float red[WARPS];
#pragma unroll
        for (int o = 16; o; o >>= 1) sum += __shfl_down_sync(0xffffffffu, sum, o);
        if (lane == 0) red[w] = sum;
        __syncthreads();
        if (w == 0) {
            sum = (lane < WARPS) ? red[lane] : 0.0f;
#pragma unroll
            for (int o = 16; o; o >>= 1) sum += __shfl_down_sync(0xffffffffu, sum, o);
            if (lane == 0) {
                *out = sum;
                g_done = 0u;                    // reset counter for next replay
            }
        }
    }
}

extern "C" void kernel_launch(void* const* d_in, const int* in_sizes, int n_in,
                              void* d_out, int out_size) {
    const float* img = (const float*)d_in[0];   // (32,1,1024,1024) fp32
    const int*   bb  = (const int*)d_in[1];     // (32,96,4) int32
    float* out = (float*)d_out;

    fused_kernel<<<GRID, NTHREADS>>>(img, bb, out);
}

// round 4
// speedup vs baseline: 1.3231x; 1.3231x over previous
#include <cuda_runtime.h>

#define BATCH 32
#define IMH 1024
#define IMW 1024
#define NBOX 96
#define WARPS 8
#define NTHREADS 256
#define ROWS_PER_WARP 8
#define ROWS_PER_BLOCK (WARPS * ROWS_PER_WARP)   // 64
#define GRID (BATCH * IMH / ROWS_PER_BLOCK)      // 512
#define EP_STRIDE 1032                           // >=1025, float4-aligned

// Per-(batch,box) rectangle sums. Zero-initialized at module load; the last
// block resets it after reading so every graph replay starts clean.
__device__ float    g_boxsum[BATCH * NBOX];
__device__ unsigned g_done;

__global__ __launch_bounds__(NTHREADS)
void fused_kernel(const float* __restrict__ img, const int* __restrict__ bb,
                  float* __restrict__ out) {
    __shared__ __align__(16) float ep_s[WARPS * EP_STRIDE];
    __shared__ int4 sbox[NBOX];

    const int t    = threadIdx.x;
    const int lane = t & 31;
    const int w    = t >> 5;
    const int blocksPerBatch = IMH / ROWS_PER_BLOCK;   // 16
    const int b       = blockIdx.x / blocksPerBatch;
    const int rowBase = (blockIdx.x % blocksPerBatch) * ROWS_PER_BLOCK + w * ROWS_PER_WARP;

    float* ep = ep_s + w * EP_STRIDE;

    // One cooperative bbox load per block.
    if (t < NBOX) sbox[t] = ((const int4*)bb)[b * NBOX + t];
    __syncthreads();

    // Each lane serves boxes lane, lane+32, lane+64.
    int   bx1[3], bx2[3], by1[3], by2[3];
    bool  bval[3];
    float bacc[3];
#pragma unroll
    for (int k = 0; k < 3; k++) {
        int4 box = sbox[lane + 32 * k];
        bx1[k] = min(max(box.x, 0), IMW);
        by1[k] = min(max(box.y, 0), IMW);
        bx2[k] = min(max(box.z, 0), IMW);
        by2[k] = min(max(box.w, 0), IMW);
        bval[k] = (bx2[k] > bx1[k]) && (by2[k] > by1[k]);
        bacc[k] = 0.0f;
    }

    const float4* imgrow = (const float4*)(img + (size_t)b * IMH * IMW);

    // Software pipeline: va = current row (being scanned), vb = next row (in flight).
    float4 va[8];
#pragma unroll
    for (int j = 0; j < 8; j++)
        va[j] = imgrow[(size_t)rowBase * (IMW / 4) + lane + 32 * j];

#pragma unroll
    for (int r = 0; r < ROWS_PER_WARP; ++r) {
        const int row = rowBase + r;

        // Prefetch next row before touching this row's data (keeps ~4KB in flight).
        float4 vb[8];
        if (r + 1 < ROWS_PER_WARP) {
#pragma unroll
            for (int j = 0; j < 8; j++)
                vb[j] = imgrow[(size_t)(row + 1) * (IMW / 4) + lane + 32 * j];
        }

        // Per-(lane, segment) 4-element sums.
        float s[8];
#pragma unroll
        for (int j = 0; j < 8; j++)
            s[j] = (va[j].x + va[j].y) + (va[j].z + va[j].w);

        // Eight independent warp scans (one per 128-wide segment), chained
        // through the scalar segment base.
        float excl[8];
        float base = 0.0f;
#pragma unroll
        for (int j = 0; j < 8; j++) {
            float sc = s[j];
#pragma unroll
            for (int o = 1; o < 32; o <<= 1) {
                float u = __shfl_up_sync(0xffffffffu, sc, o);
                if (lane >= o) sc += u;
            }
            excl[j] = (sc - s[j]) + base;
            base += __shfl_sync(0xffffffffu, sc, 31);   // segment total
        }

        // Write exclusive prefixes: 8 conflict-free STS.128 per row.
#pragma unroll
        for (int j = 0; j < 8; j++) {
            float4 p;
            p.x = excl[j];
            p.y = p.x + va[j].x;
            p.z = p.y + va[j].y;
            p.w = p.z + va[j].z;
            *(float4*)(ep + 128 * j + 4 * lane) = p;
        }
        if (lane == 31) ep[IMW] = base;
        __syncwarp();

        // Serve this row for all 96 boxes (3 per lane).
#pragma unroll
        for (int k = 0; k < 3; k++) {
            if (bval[k] && by1[k] <= row && row < by2[k])
                bacc[k] += ep[bx2[k]] - ep[bx1[k]];
        }
        __syncwarp();   // ep reused next row

        // Rotate buffers (renamed away by full unroll).
        if (r + 1 < ROWS_PER_WARP) {
#pragma unroll
            for (int j = 0; j < 8; j++)
                va[j] = vb[j];
        }
    }

#pragma unroll
    for (int k = 0; k < 3; k++)
        if (bval[k] && bacc[k] != 0.0f)
            atomicAdd(&g_boxsum[b * NBOX + lane + 32 * k], bacc[k]);

    // ---- last-block epilogue: loss + state reset ----
    __shared__ unsigned lastflag;
    __threadfence();
    if (t == 0) {
        unsigned vdone = atomicAdd(&g_done, 1u);
        lastflag = (vdone == (unsigned)(gridDim.x - 1));
    }
    __syncthreads();

    if (lastflag) {
        float sum = 0.0f;
#pragma unroll 4
        for (int i = t; i < BATCH * NBOX; i += NTHREADS) {
            float sv = __ldcg(&g_boxsum[i]);
            g_boxsum[i] = 0.0f;                 // reset for next replay
            float d = 1.0f - sv;                // invalid boxes stayed 0 -> contribute 1
            sum += (d > 0.0f) ? d : 0.0f;
        }
        __shared__ float red[WARPS];
#pragma unroll
        for (int o = 16; o; o >>= 1) sum += __shfl_down_sync(0xffffffffu, sum, o);
        if (lane == 0) red[w] = sum;
        __syncthreads();
        if (w == 0) {
            sum = (lane < WARPS) ? red[lane] : 0.0f;
#pragma unroll
            for (int o = 16; o; o >>= 1) sum += __shfl_down_sync(0xffffffffu, sum, o);
            if (lane == 0) {
                *out = sum;
                g_done = 0u;                    // reset counter for next replay
            }
        }
    }
}

extern "C" void kernel_launch(void* const* d_in, const int* in_sizes, int n_in,
                              void* d_out, int out_size) {
    const float* img = (const float*)d_in[0];   // (32,1,1024,1024) fp32
    const int*   bb  = (const int*)d_in[1];     // (32,96,4) int32
    float* out = (float*)d_out;

    fused_kernel<<<GRID, NTHREADS>>>(img, bb, out);
}